// round 9
// baseline (speedup 1.0000x reference)
#include <cuda_runtime.h>
#include <cuda_fp16.h>
#include <cstdint>

// ---------------- problem constants ----------------
#define N_E      8192
#define EDIM     256
#define BPOS     8192          // 8 * 32 * 32 positions
#define ZQ_ELEMS 2097152       // 8 * 256 * 32 * 32

// ---------------- pass-1 tiling ----------------
#define GM       64            // positions per CTA
#define BN       128           // codes per chunk (two 64-row halves)
#define NHALF    64            // 4096 / 64 halves per split
#define NSPLIT   2
#define P1THREADS 256          // 8 warps: 2m x 4n, warp tile 32x16 per half
#define CAP      64
#define MARGIN   1.0f

// ---------------- static device scratch ----------------
// fp16 operands; [row][k] row-major, 16B-chunk swizzle by (row&7)
__device__ __align__(128) __half g_Ah[BPOS * EDIM];
__device__ __align__(128) __half g_Wh[N_E * EDIM];
__device__ int g_ccnt[BPOS];
__device__ int g_cand[BPOS * CAP];
__device__ int g_ind[BPOS];
__device__ float g_losspart[2048];

// ---------------- helpers ----------------
__device__ __forceinline__ uint32_t smem_u32(const void* p) {
    uint32_t a;
    asm("{ .reg .u64 t; cvta.to.shared.u64 t, %1; cvt.u32.u64 %0, t; }" : "=r"(a) : "l"(p));
    return a;
}
__device__ __forceinline__ uint32_t encf(float f) {
    uint32_t u = __float_as_uint(f);
    return (u & 0x80000000u) ? ~u : (u | 0x80000000u);
}
__device__ __forceinline__ float decf(uint32_t u) {
    return (u & 0x80000000u) ? __uint_as_float(u & 0x7FFFFFFFu) : __uint_as_float(~u);
}
__device__ __forceinline__ uint32_t packh2(float lo, float hi) {
    __half2 h = __floats2half2_rn(lo, hi);
    return *(uint32_t*)&h;
}

#define LDSM4(r0, r1, r2, r3, addr) \
    asm volatile("ldmatrix.sync.aligned.m8n8.x4.shared.b16 {%0,%1,%2,%3},[%4];" \
        : "=r"(r0), "=r"(r1), "=r"(r2), "=r"(r3) : "r"(addr))

#define MMA_F16ACC(d0, d1, a0, a1, a2, a3, b0, b1) \
    asm volatile("mma.sync.aligned.m16n8k16.row.col.f16.f16.f16.f16 " \
        "{%0,%1},{%2,%3,%4,%5},{%6,%7},{%0,%1};" \
        : "+r"(d0), "+r"(d1) \
        : "r"(a0), "r"(a1), "r"(a2), "r"(a3), "r"(b0), "r"(b1))

#define CP16(dst, src) \
    asm volatile("cp.async.cg.shared.global [%0], [%1], 16;" :: "r"(dst), "l"(src))
#define CP_COMMIT() asm volatile("cp.async.commit_group;" ::: "memory")
#define CP_WAIT1()  asm volatile("cp.async.wait_group 1;" ::: "memory")
#define CP_WAIT0()  asm volatile("cp.async.wait_group 0;" ::: "memory")

// =====================================================================
// Fused prep: blocks [0,1024) convert W, [1024,1536) convert/transpose A,
// [1536,1568) reset counters.  (rows are 512B: 256 x fp16)
// =====================================================================
__global__ void prep_kernel(const float* __restrict__ z,
                            const float* __restrict__ W) {
    __shared__ float s[32][129];
    int blk = blockIdx.x;
    int t   = threadIdx.x;

    if (blk < 1024) {
        int c  = blk * 256 + t;            // 16B chunks (8 halves)
        int n  = c >> 5;
        int kc = c & 31;
        const float4* src = (const float4*)(W + (size_t)n * EDIM + kc * 8);
        float4 v0 = src[0], v1 = src[1];
        uint4 o;
        o.x = packh2(v0.x, v0.y);
        o.y = packh2(v0.z, v0.w);
        o.z = packh2(v1.x, v1.y);
        o.w = packh2(v1.z, v1.w);
        uint32_t off = (uint32_t)n * 512 + ((uint32_t)(kc ^ (n & 7)) << 4);
        *(uint4*)((char*)g_Wh + off) = o;
    } else if (blk < 1536) {
        int tile = blk - 1024;             // mt128*8 + ks
        int mt   = tile >> 3;
        int ks   = tile & 7;
        int m0   = mt * 128;
        int b    = m0 >> 10;
        int hw0  = m0 & 1023;
        #pragma unroll
        for (int r = 0; r < 16; r++) {
            int idx = t + r * 256;
            int kk  = idx >> 7;
            int mm  = idx & 127;
            s[kk][mm] = z[(size_t)b * (EDIM * 1024) + (size_t)(ks * 32 + kk) * 1024 + hw0 + mm];
        }
        __syncthreads();
        int m    = t & 127;
        int half = t >> 7;
        #pragma unroll
        for (int q = 0; q < 2; q++) {
            int kcl = half * 2 + q;
            uint4 o;
            uint32_t* op = (uint32_t*)&o;
            #pragma unroll
            for (int pp = 0; pp < 4; pp++) {
                int kl = kcl * 8 + pp * 2;
                op[pp] = packh2(s[kl][m], s[kl + 1][m]);
            }
            int kc = ks * 4 + kcl;
            uint32_t off = (uint32_t)(m0 + m) * 512
                         + ((uint32_t)(kc ^ (m & 7)) << 4);
            *(uint4*)((char*)g_Ah + off) = o;
        }
    } else {
        int p = (blk - 1536) * 256 + t;
        if (p < BPOS) g_ccnt[p] = 0;
    }
}

// =====================================================================
// Pass 1: fp16 HMMA + max/candidate collection.
// OCCUPANCY 2 + double-buffered B (two 32KB half-buffers, 64 codes each).
// grid (128 mtiles, 2 splits) x 256 threads (8 warps, 2m x 4n)
// smem: pmax[64] @0 (1KB pad), A 32KB @1024, B0/B1 2x32KB  => 97KB
// =====================================================================
#define P1_SMEM (1024 + 32768 + 2 * 32768)

__global__ void __launch_bounds__(P1THREADS, 2)
pass1_kernel() {
    extern __shared__ char dsm[];
    uint32_t sbase = smem_u32(dsm);
    uint32_t smA   = sbase + 1024;
    uint32_t smB   = sbase + 1024 + 32768;

    const int t     = threadIdx.x;
    const int lane  = t & 31;
    const int w     = t >> 5;
    const int wm    = w & 1;           // m-half (32 rows)
    const int wn    = w >> 1;          // n-group (16 cols per half)
    const int mtile = blockIdx.x;      // 0..127 (64-row tiles)
    const int split = blockIdx.y;

    uint32_t* pmax = (uint32_t*)dsm;
    if (t < GM) pmax[t] = encf(-3.4e38f);

    const char* srcW = (const char*)g_Wh + (size_t)(split * 4096) * 512;

    // prologue: A (32KB) + B half 0 in group 0; B half 1 in group 1
    {
        const char* srcA = (const char*)g_Ah + (size_t)mtile * (GM * 512);
        #pragma unroll
        for (int i = 0; i < 8; i++) {
            uint32_t off = (uint32_t)(t + i * 256) * 16;
            CP16(smA + off, srcA + off);
        }
        #pragma unroll
        for (int i = 0; i < 8; i++) {
            uint32_t off = (uint32_t)(t + i * 256) * 16;
            CP16(smB + off, srcW + off);
        }
        CP_COMMIT();
        #pragma unroll
        for (int i = 0; i < 8; i++) {
            uint32_t off = (uint32_t)(t + i * 256) * 16;
            CP16(smB + 32768u + off, srcW + 32768u + off);
        }
        CP_COMMIT();
    }

    // ldmatrix lane geometry
    const int lane7 = lane & 7;
    const int a_m   = wm * 32 + lane7 + (lane & 8);
    const int a_ksl = (lane >> 4) & 1;
    const uint32_t aBase0 = smA + (uint32_t)a_m * 512;
    const uint32_t aBase1 = smA + (uint32_t)(a_m + 16) * 512;
    const int b_nl  = wn * 16 + lane7 + ((lane >> 4) & 1) * 8;   // row in 64-row half
    const int b_ksl = (lane >> 3) & 1;

    // acc[mt][ (half&1)*2 + nt ][row-half], f16x2
    uint32_t acc[2][4][2];
    #pragma unroll
    for (int i = 0; i < 2; i++)
        #pragma unroll
        for (int j = 0; j < 4; j++) { acc[i][j][0] = 0u; acc[i][j][1] = 0u; }

    for (int h = 0; h < NHALF; h++) {
        if (h < NHALF - 1) { CP_WAIT1(); } else { CP_WAIT0(); }
        __syncthreads();

        const uint32_t smBc = smB + (uint32_t)(h & 1) * 32768u;
        const uint32_t bBase = smBc + (uint32_t)b_nl * 512;
        const int slot = (h & 1) * 2;

        #pragma unroll
        for (int ks = 0; ks < 16; ks++) {
            uint32_t a0, a1, a2, a3, c0, c1, c2, c3;
            uint32_t aoff = (uint32_t)(((2 * ks + a_ksl) ^ lane7) << 4);
            LDSM4(a0, a1, a2, a3, aBase0 + aoff);
            LDSM4(c0, c1, c2, c3, aBase1 + aoff);
            uint32_t r0, r1, r2, r3;
            uint32_t boff = (uint32_t)(((2 * ks + b_ksl) ^ lane7) << 4);
            LDSM4(r0, r1, r2, r3, bBase + boff);
            MMA_F16ACC(acc[0][slot][0],   acc[0][slot][1],   a0, a1, a2, a3, r0, r1);
            MMA_F16ACC(acc[0][slot+1][0], acc[0][slot+1][1], a0, a1, a2, a3, r2, r3);
            MMA_F16ACC(acc[1][slot][0],   acc[1][slot][1],   c0, c1, c2, c3, r0, r1);
            MMA_F16ACC(acc[1][slot+1][0], acc[1][slot+1][1], c0, c1, c2, c3, r2, r3);
        }
        __syncthreads();   // LDSM done -> this buffer may be overwritten

        if (h + 2 < NHALF) {
            uint32_t dstB = smB + (uint32_t)(h & 1) * 32768u;
            const char* src = srcW + (size_t)(h + 2) * 32768u;
            #pragma unroll
            for (int i = 0; i < 8; i++) {
                uint32_t off = (uint32_t)(t + i * 256) * 16;
                CP16(dstB + off, src + off);
            }
            CP_COMMIT();
        }

        if (h & 1) {
            // ---- epilogue over the full 128-code chunk (overlaps load) ----
            const int cn = h >> 1;
            const int rbase = wm * 32 + (lane >> 2);
            #pragma unroll
            for (int mt = 0; mt < 2; mt++) {
                #pragma unroll
                for (int hh = 0; hh < 2; hh++) {
                    __half2 m2 = *(__half2*)&acc[mt][0][hh];
                    #pragma unroll
                    for (int j = 1; j < 4; j++)
                        m2 = __hmax2(m2, *(__half2*)&acc[mt][j][hh]);
                    float mx = fmaxf(__low2float(m2), __high2float(m2));
                    mx = fmaxf(mx, __shfl_xor_sync(0xffffffffu, mx, 1));
                    mx = fmaxf(mx, __shfl_xor_sync(0xffffffffu, mx, 2));
                    if ((lane & 3) == 0) {
                        int row = rbase + mt * 16 + 8 * hh;
                        atomicMax(&pmax[row], encf(mx));
                    }
                }
            }
            // threshold may miss in-flight maxes from this chunk: superset-safe
            #pragma unroll
            for (int mt = 0; mt < 2; mt++) {
                #pragma unroll
                for (int hh = 0; hh < 2; hh++) {
                    int row = rbase + mt * 16 + 8 * hh;
                    float thr = decf(pmax[row]) - MARGIN;
                    int p = mtile * GM + row;
                    #pragma unroll
                    for (int j = 0; j < 4; j++) {
                        float v0 = __low2float(*(__half2*)&acc[mt][j][hh]);
                        float v1 = __high2float(*(__half2*)&acc[mt][j][hh]);
                        #pragma unroll
                        for (int cc = 0; cc < 2; cc++) {
                            float v = cc ? v1 : v0;
                            if (v >= thr) {
                                int n_abs = split * 4096 + cn * BN + (j >> 1) * 64
                                          + wn * 16 + (j & 1) * 8 + 2 * (lane & 3) + cc;
                                int slotc = atomicAdd(&g_ccnt[p], 1);
                                if (slotc < CAP) g_cand[p * CAP + slotc] = n_abs;
                            }
                        }
                    }
                }
            }
            // reset accumulators
            #pragma unroll
            for (int i = 0; i < 2; i++)
                #pragma unroll
                for (int j = 0; j < 4; j++) { acc[i][j][0] = 0u; acc[i][j][1] = 0u; }
        }
    }
}

// =====================================================================
// Pass 2: exact fp32 argmax over candidate set (one warp per position)
// =====================================================================
__global__ void pass2_kernel(const float* __restrict__ z,
                             const float* __restrict__ W) {
    int p = blockIdx.x * 8 + (threadIdx.x >> 5);
    if (p >= BPOS) return;
    int lane = threadIdx.x & 31;
    int b  = p >> 10;
    int hw = p & 1023;
    float zr[8];
    #pragma unroll
    for (int j = 0; j < 8; j++)
        zr[j] = z[(size_t)b * (EDIM * 1024) + (size_t)(lane * 8 + j) * 1024 + hw];

    int cnt = g_ccnt[p];
    float best_v = -3.4e38f;
    int   best_i = 0x7FFFFFFF;

    if (cnt <= CAP) {
        for (int c = 0; c < cnt; c++) {
            int n = g_cand[p * CAP + c];
            const float* wr = W + (size_t)n * EDIM + lane * 8;
            float s = 0.0f;
            #pragma unroll
            for (int j = 0; j < 8; j++) s = fmaf(zr[j], wr[j], s);
            #pragma unroll
            for (int off = 16; off > 0; off >>= 1)
                s += __shfl_xor_sync(0xffffffffu, s, off);
            if (s > best_v || (s == best_v && n < best_i)) { best_v = s; best_i = n; }
        }
    } else {
        for (int n = 0; n < N_E; n++) {   // overflow fallback (never expected)
            const float* wr = W + (size_t)n * EDIM + lane * 8;
            float s = 0.0f;
            #pragma unroll
            for (int j = 0; j < 8; j++) s = fmaf(zr[j], wr[j], s);
            #pragma unroll
            for (int off = 16; off > 0; off >>= 1)
                s += __shfl_xor_sync(0xffffffffu, s, off);
            if (s > best_v) { best_v = s; best_i = n; }
        }
    }
    if (lane == 0) g_ind[p] = best_i;
}

// =====================================================================
// z_q gather (float4) + loss partials + optional ind write
// =====================================================================
__global__ void zq_loss_kernel(const float* __restrict__ z,
                               const float* __restrict__ W,
                               float* __restrict__ out,
                               int write_ind) {
    __shared__ float red[8];
    int t  = threadIdx.x;
    int e4 = (blockIdx.x * 256 + t) * 4;
    int hw = e4 & 1023;
    int d  = (e4 >> 10) & 255;
    int bb = e4 >> 18;
    int pb = (bb << 10) | hw;
    float4 zv = *(const float4*)(z + e4);
    int n0 = g_ind[pb], n1 = g_ind[pb + 1], n2 = g_ind[pb + 2], n3 = g_ind[pb + 3];
    float4 wv;
    wv.x = W[(size_t)n0 * EDIM + d];
    wv.y = W[(size_t)n1 * EDIM + d];
    wv.z = W[(size_t)n2 * EDIM + d];
    wv.w = W[(size_t)n3 * EDIM + d];
    *(float4*)(out + e4) = wv;
    float dx = wv.x - zv.x, dy = wv.y - zv.y, dz = wv.z - zv.z, dw = wv.w - zv.w;
    float s = dx * dx + dy * dy + dz * dz + dw * dw;
    #pragma unroll
    for (int off = 16; off > 0; off >>= 1)
        s += __shfl_xor_sync(0xffffffffu, s, off);
    if ((t & 31) == 0) red[t >> 5] = s;
    __syncthreads();
    if (t < 8) {
        float v = red[t];
        #pragma unroll
        for (int off = 4; off > 0; off >>= 1)
            v += __shfl_xor_sync(0xffu, v, off);
        if (t == 0) g_losspart[blockIdx.x] = v;
    }
    if (write_ind && blockIdx.x < 8) {
        int base = blockIdx.x * 1024 + t * 4;
        out[ZQ_ELEMS + 1 + base + 0] = (float)g_ind[base + 0];
        out[ZQ_ELEMS + 1 + base + 1] = (float)g_ind[base + 1];
        out[ZQ_ELEMS + 1 + base + 2] = (float)g_ind[base + 2];
        out[ZQ_ELEMS + 1 + base + 3] = (float)g_ind[base + 3];
    }
}

__global__ void finalize_kernel(float* __restrict__ out) {
    __shared__ float red[8];
    float s = 0.0f;
    for (int i = threadIdx.x; i < 2048; i += 256) s += g_losspart[i];
    #pragma unroll
    for (int off = 16; off > 0; off >>= 1)
        s += __shfl_xor_sync(0xffffffffu, s, off);
    if ((threadIdx.x & 31) == 0) red[threadIdx.x >> 5] = s;
    __syncthreads();
    if (threadIdx.x < 8) {
        float v = red[threadIdx.x];
        #pragma unroll
        for (int off = 4; off > 0; off >>= 1)
            v += __shfl_xor_sync(0xffu, v, off);
        if (threadIdx.x == 0)
            out[ZQ_ELEMS] = 2.25f * v / (float)ZQ_ELEMS;
    }
}

// =====================================================================
extern "C" void kernel_launch(void* const* d_in, const int* in_sizes, int n_in,
                              void* d_out, int out_size) {
    const float* z = (const float*)d_in[0];   // (8, 256, 32, 32)
    const float* W = (const float*)d_in[1];   // (8192, 256)
    float* out = (float*)d_out;

    cudaFuncSetAttribute(pass1_kernel,
                         cudaFuncAttributeMaxDynamicSharedMemorySize, P1_SMEM);

    int write_ind = (out_size >= ZQ_ELEMS + 1 + BPOS) ? 1 : 0;

    prep_kernel<<<1568, 256>>>(z, W);
    pass1_kernel<<<dim3(128, NSPLIT), P1THREADS, P1_SMEM>>>();
    pass2_kernel<<<BPOS / 8, 256>>>(z, W);
    zq_loss_kernel<<<ZQ_ELEMS / 1024, 256>>>(z, W, out, write_ind);
    if (out_size > ZQ_ELEMS) {
        finalize_kernel<<<1, 256>>>(out);
    }
}

// round 10
// speedup vs baseline: 1.2651x; 1.2651x over previous
#include <cuda_runtime.h>
#include <cuda_fp16.h>
#include <cstdint>

// ---------------- problem constants ----------------
#define N_E      8192
#define EDIM     256
#define BPOS     8192          // 8 * 32 * 32 positions
#define ZQ_ELEMS 2097152       // 8 * 256 * 32 * 32

// ---------------- pass-1 tiling ----------------
#define GM       64            // positions per CTA
#define BN       128           // codes per chunk
#define NSPLIT   2
#define NCHUNK   32            // 4096 / 128 per split
#define P1THREADS 256          // 8 warps: 2m x 4n, warp tile 32x32
#define CAP      64
#define MARGIN   1.0f

// ---------------- static device scratch ----------------
// fp16 operands; [row][k] row-major with 16B-chunk swizzle by (row&7)
__device__ __align__(128) __half g_Ah[BPOS * EDIM];
__device__ __align__(128) __half g_Wh[N_E * EDIM];
__device__ int g_ccnt[BPOS];
__device__ int g_cand[BPOS * CAP];
__device__ int g_ind[BPOS];
__device__ float g_losspart[2048];

// ---------------- helpers ----------------
__device__ __forceinline__ uint32_t smem_u32(const void* p) {
    uint32_t a;
    asm("{ .reg .u64 t; cvta.to.shared.u64 t, %1; cvt.u32.u64 %0, t; }" : "=r"(a) : "l"(p));
    return a;
}
__device__ __forceinline__ uint32_t encf(float f) {
    uint32_t u = __float_as_uint(f);
    return (u & 0x80000000u) ? ~u : (u | 0x80000000u);
}
__device__ __forceinline__ float decf(uint32_t u) {
    return (u & 0x80000000u) ? __uint_as_float(u & 0x7FFFFFFFu) : __uint_as_float(~u);
}
__device__ __forceinline__ uint32_t packh2(float lo, float hi) {
    __half2 h = __floats2half2_rn(lo, hi);
    return *(uint32_t*)&h;
}

#define LDSM4(r0, r1, r2, r3, addr) \
    asm volatile("ldmatrix.sync.aligned.m8n8.x4.shared.b16 {%0,%1,%2,%3},[%4];" \
        : "=r"(r0), "=r"(r1), "=r"(r2), "=r"(r3) : "r"(addr))

#define MMA_F16ACC(d0, d1, a0, a1, a2, a3, b0, b1) \
    asm volatile("mma.sync.aligned.m16n8k16.row.col.f16.f16.f16.f16 " \
        "{%0,%1},{%2,%3,%4,%5},{%6,%7},{%0,%1};" \
        : "+r"(d0), "+r"(d1) \
        : "r"(a0), "r"(a1), "r"(a2), "r"(a3), "r"(b0), "r"(b1))

#define CP16(dst, src) \
    asm volatile("cp.async.cg.shared.global [%0], [%1], 16;" :: "r"(dst), "l"(src))
#define CP_COMMIT() asm volatile("cp.async.commit_group;" ::: "memory")
#define CP_WAIT0()  asm volatile("cp.async.wait_group 0;" ::: "memory")

// =====================================================================
// Fused prep: blocks [0,1024) convert W, [1024,1536) convert/transpose A,
// [1536,1568) reset counters.  (rows are 512B: 256 x fp16)
// =====================================================================
__global__ void prep_kernel(const float* __restrict__ z,
                            const float* __restrict__ W) {
    __shared__ float s[32][129];
    int blk = blockIdx.x;
    int t   = threadIdx.x;

    if (blk < 1024) {
        int c  = blk * 256 + t;            // 16B chunks (8 halves)
        int n  = c >> 5;
        int kc = c & 31;
        const float4* src = (const float4*)(W + (size_t)n * EDIM + kc * 8);
        float4 v0 = src[0], v1 = src[1];
        uint4 o;
        o.x = packh2(v0.x, v0.y);
        o.y = packh2(v0.z, v0.w);
        o.z = packh2(v1.x, v1.y);
        o.w = packh2(v1.z, v1.w);
        uint32_t off = (uint32_t)n * 512 + ((uint32_t)(kc ^ (n & 7)) << 4);
        *(uint4*)((char*)g_Wh + off) = o;
    } else if (blk < 1536) {
        int tile = blk - 1024;             // mt128*8 + ks
        int mt   = tile >> 3;
        int ks   = tile & 7;
        int m0   = mt * 128;
        int b    = m0 >> 10;
        int hw0  = m0 & 1023;
        #pragma unroll
        for (int r = 0; r < 16; r++) {
            int idx = t + r * 256;
            int kk  = idx >> 7;
            int mm  = idx & 127;
            s[kk][mm] = z[(size_t)b * (EDIM * 1024) + (size_t)(ks * 32 + kk) * 1024 + hw0 + mm];
        }
        __syncthreads();
        int m    = t & 127;
        int half = t >> 7;
        #pragma unroll
        for (int q = 0; q < 2; q++) {
            int kcl = half * 2 + q;
            uint4 o;
            uint32_t* op = (uint32_t*)&o;
            #pragma unroll
            for (int pp = 0; pp < 4; pp++) {
                int kl = kcl * 8 + pp * 2;
                op[pp] = packh2(s[kl][m], s[kl + 1][m]);
            }
            int kc = ks * 4 + kcl;
            uint32_t off = (uint32_t)(m0 + m) * 512
                         + ((uint32_t)(kc ^ (m & 7)) << 4);
            *(uint4*)((char*)g_Ah + off) = o;
        }
    } else {
        int p = (blk - 1536) * 256 + t;
        if (p < BPOS) g_ccnt[p] = 0;
    }
}

// =====================================================================
// Pass 1: fp16 HMMA + max/candidate collection.  OCCUPANCY 2.
// Single-buffered B, but the NEXT chunk's load is issued BEFORE the
// epilogue so it overlaps; epilogue uses half2 fast-reject.
// grid (128 mtiles, 2 splits) x 256 threads (8 warps, 2m x 4n)
// smem: pmax[64] @0 (1KB pad), A 32KB @1024, B 64KB @33792  => 97KB
// =====================================================================
#define P1_SMEM (1024 + 32768 + 65536)

__global__ void __launch_bounds__(P1THREADS, 2)
pass1_kernel() {
    extern __shared__ char dsm[];
    uint32_t sbase = smem_u32(dsm);
    uint32_t smA   = sbase + 1024;
    uint32_t smB   = sbase + 1024 + 32768;

    const int t     = threadIdx.x;
    const int lane  = t & 31;
    const int w     = t >> 5;
    const int wm    = w & 1;           // m-half (32 rows)
    const int wn    = w >> 1;          // n-quarter (32 cols)
    const int mtile = blockIdx.x;      // 0..127 (64-row tiles)
    const int split = blockIdx.y;

    uint32_t* pmax = (uint32_t*)dsm;
    if (t < GM) pmax[t] = encf(-3.4e38f);

    const char* srcW = (const char*)g_Wh + (size_t)(split * 4096) * 512;

    // prologue: A (32KB) + B chunk 0 (64KB), one commit group
    {
        const char* srcA = (const char*)g_Ah + (size_t)mtile * (GM * 512);
        #pragma unroll
        for (int i = 0; i < 8; i++) {
            uint32_t off = (uint32_t)(t + i * 256) * 16;
            CP16(smA + off, srcA + off);
        }
        #pragma unroll
        for (int i = 0; i < 16; i++) {
            uint32_t off = (uint32_t)(t + i * 256) * 16;
            CP16(smB + off, srcW + off);
        }
        CP_COMMIT();
    }

    // ldmatrix lane geometry
    const int lane7 = lane & 7;
    const int a_m   = wm * 32 + lane7 + (lane & 8);
    const int a_ksl = (lane >> 4) & 1;
    const uint32_t aBase0 = smA + (uint32_t)a_m * 512;
    const uint32_t aBase1 = smA + (uint32_t)(a_m + 16) * 512;
    const int b_nl  = wn * 32 + lane7 + ((lane >> 4) & 1) * 8;
    const int b_ksl = (lane >> 3) & 1;

    for (int cn = 0; cn < NCHUNK; cn++) {
        CP_WAIT0();
        __syncthreads();               // B(cn) visible to all warps

        uint32_t acc[2][4][2];
        #pragma unroll
        for (int i = 0; i < 2; i++)
            #pragma unroll
            for (int j = 0; j < 4; j++) { acc[i][j][0] = 0u; acc[i][j][1] = 0u; }

        #pragma unroll
        for (int ks = 0; ks < 16; ks++) {
            uint32_t a0, a1, a2, a3, c0, c1, c2, c3;
            uint32_t aoff = (uint32_t)(((2 * ks + a_ksl) ^ lane7) << 4);
            LDSM4(a0, a1, a2, a3, aBase0 + aoff);
            LDSM4(c0, c1, c2, c3, aBase1 + aoff);
            uint32_t boff = (uint32_t)(((2 * ks + b_ksl) ^ lane7) << 4);
            #pragma unroll
            for (int ntp = 0; ntp < 2; ntp++) {
                uint32_t r0, r1, r2, r3;
                uint32_t baddr = smB + (uint32_t)(b_nl + ntp * 16) * 512 + boff;
                LDSM4(r0, r1, r2, r3, baddr);
                MMA_F16ACC(acc[0][2*ntp][0],   acc[0][2*ntp][1],   a0, a1, a2, a3, r0, r1);
                MMA_F16ACC(acc[0][2*ntp+1][0], acc[0][2*ntp+1][1], a0, a1, a2, a3, r2, r3);
                MMA_F16ACC(acc[1][2*ntp][0],   acc[1][2*ntp][1],   c0, c1, c2, c3, r0, r1);
                MMA_F16ACC(acc[1][2*ntp+1][0], acc[1][2*ntp+1][1], c0, c1, c2, c3, r2, r3);
            }
        }
        __syncthreads();               // everyone done reading B buffer

        // issue NEXT chunk's B load now; it overlaps the epilogue below
        if (cn + 1 < NCHUNK) {
            const char* src = srcW + (size_t)(cn + 1) * 65536u;
            #pragma unroll
            for (int i = 0; i < 16; i++) {
                uint32_t off = (uint32_t)(t + i * 256) * 16;
                CP16(smB + off, src + off);
            }
            CP_COMMIT();
        }

        // ---- epilogue (overlaps the in-flight load; no B smem access) ----
        const int rbase = wm * 32 + (lane >> 2);
        #pragma unroll
        for (int mt = 0; mt < 2; mt++) {
            #pragma unroll
            for (int h = 0; h < 2; h++) {
                __half2 m2 = *(__half2*)&acc[mt][0][h];
                #pragma unroll
                for (int nt = 1; nt < 4; nt++)
                    m2 = __hmax2(m2, *(__half2*)&acc[mt][nt][h]);
                float mx = fmaxf(__low2float(m2), __high2float(m2));
                mx = fmaxf(mx, __shfl_xor_sync(0xffffffffu, mx, 1));
                mx = fmaxf(mx, __shfl_xor_sync(0xffffffffu, mx, 2));
                if ((lane & 3) == 0) {
                    int row = rbase + mt * 16 + 8 * h;
                    atomicMax(&pmax[row], encf(mx));
                }
            }
        }
        // candidate pass: half2 fast-reject (round-down thr => superset-safe)
        #pragma unroll
        for (int mt = 0; mt < 2; mt++) {
            #pragma unroll
            for (int h = 0; h < 2; h++) {
                int row = rbase + mt * 16 + 8 * h;
                float thr = decf(pmax[row]) - MARGIN;
                __half thr_h = __float2half_rd(thr);
                __half2 thr2 = __halves2half2(thr_h, thr_h);
                uint32_t any = 0;
                #pragma unroll
                for (int j = 0; j < 4; j++) {
                    __half2 ge = __hge2(*(__half2*)&acc[mt][j][h], thr2);
                    any |= *(uint32_t*)&ge;
                }
                if (any) {
                    int p = mtile * GM + row;
                    #pragma unroll
                    for (int j = 0; j < 4; j++) {
                        float v0 = __low2float(*(__half2*)&acc[mt][j][h]);
                        float v1 = __high2float(*(__half2*)&acc[mt][j][h]);
                        #pragma unroll
                        for (int cc = 0; cc < 2; cc++) {
                            float v = cc ? v1 : v0;
                            if (v >= thr) {
                                int n_abs = split * 4096 + cn * BN + wn * 32
                                          + j * 8 + 2 * (lane & 3) + cc;
                                int slot = atomicAdd(&g_ccnt[p], 1);
                                if (slot < CAP) g_cand[p * CAP + slot] = n_abs;
                            }
                        }
                    }
                }
            }
        }
    }
}

// =====================================================================
// Pass 2: exact fp32 argmax over candidate set (one warp per position)
// =====================================================================
__global__ void pass2_kernel(const float* __restrict__ z,
                             const float* __restrict__ W) {
    int p = blockIdx.x * 8 + (threadIdx.x >> 5);
    if (p >= BPOS) return;
    int lane = threadIdx.x & 31;
    int b  = p >> 10;
    int hw = p & 1023;
    float zr[8];
    #pragma unroll
    for (int j = 0; j < 8; j++)
        zr[j] = z[(size_t)b * (EDIM * 1024) + (size_t)(lane * 8 + j) * 1024 + hw];

    int cnt = g_ccnt[p];
    float best_v = -3.4e38f;
    int   best_i = 0x7FFFFFFF;

    if (cnt <= CAP) {
        for (int c = 0; c < cnt; c++) {
            int n = g_cand[p * CAP + c];
            const float* wr = W + (size_t)n * EDIM + lane * 8;
            float s = 0.0f;
            #pragma unroll
            for (int j = 0; j < 8; j++) s = fmaf(zr[j], wr[j], s);
            #pragma unroll
            for (int off = 16; off > 0; off >>= 1)
                s += __shfl_xor_sync(0xffffffffu, s, off);
            if (s > best_v || (s == best_v && n < best_i)) { best_v = s; best_i = n; }
        }
    } else {
        for (int n = 0; n < N_E; n++) {   // overflow fallback (never expected)
            const float* wr = W + (size_t)n * EDIM + lane * 8;
            float s = 0.0f;
            #pragma unroll
            for (int j = 0; j < 8; j++) s = fmaf(zr[j], wr[j], s);
            #pragma unroll
            for (int off = 16; off > 0; off >>= 1)
                s += __shfl_xor_sync(0xffffffffu, s, off);
            if (s > best_v) { best_v = s; best_i = n; }
        }
    }
    if (lane == 0) g_ind[p] = best_i;
}

// =====================================================================
// z_q gather (float4) + loss partials + optional ind write
// =====================================================================
__global__ void zq_loss_kernel(const float* __restrict__ z,
                               const float* __restrict__ W,
                               float* __restrict__ out,
                               int write_ind) {
    __shared__ float red[8];
    int t  = threadIdx.x;
    int e4 = (blockIdx.x * 256 + t) * 4;
    int hw = e4 & 1023;
    int d  = (e4 >> 10) & 255;
    int bb = e4 >> 18;
    int pb = (bb << 10) | hw;
    float4 zv = *(const float4*)(z + e4);
    int n0 = g_ind[pb], n1 = g_ind[pb + 1], n2 = g_ind[pb + 2], n3 = g_ind[pb + 3];
    float4 wv;
    wv.x = W[(size_t)n0 * EDIM + d];
    wv.y = W[(size_t)n1 * EDIM + d];
    wv.z = W[(size_t)n2 * EDIM + d];
    wv.w = W[(size_t)n3 * EDIM + d];
    *(float4*)(out + e4) = wv;
    float dx = wv.x - zv.x, dy = wv.y - zv.y, dz = wv.z - zv.z, dw = wv.w - zv.w;
    float s = dx * dx + dy * dy + dz * dz + dw * dw;
    #pragma unroll
    for (int off = 16; off > 0; off >>= 1)
        s += __shfl_xor_sync(0xffffffffu, s, off);
    if ((t & 31) == 0) red[t >> 5] = s;
    __syncthreads();
    if (t < 8) {
        float v = red[t];
        #pragma unroll
        for (int off = 4; off > 0; off >>= 1)
            v += __shfl_xor_sync(0xffu, v, off);
        if (t == 0) g_losspart[blockIdx.x] = v;
    }
    if (write_ind && blockIdx.x < 8) {
        int base = blockIdx.x * 1024 + t * 4;
        out[ZQ_ELEMS + 1 + base + 0] = (float)g_ind[base + 0];
        out[ZQ_ELEMS + 1 + base + 1] = (float)g_ind[base + 1];
        out[ZQ_ELEMS + 1 + base + 2] = (float)g_ind[base + 2];
        out[ZQ_ELEMS + 1 + base + 3] = (float)g_ind[base + 3];
    }
}

__global__ void finalize_kernel(float* __restrict__ out) {
    __shared__ float red[8];
    float s = 0.0f;
    for (int i = threadIdx.x; i < 2048; i += 256) s += g_losspart[i];
    #pragma unroll
    for (int off = 16; off > 0; off >>= 1)
        s += __shfl_xor_sync(0xffffffffu, s, off);
    if ((threadIdx.x & 31) == 0) red[threadIdx.x >> 5] = s;
    __syncthreads();
    if (threadIdx.x < 8) {
        float v = red[threadIdx.x];
        #pragma unroll
        for (int off = 4; off > 0; off >>= 1)
            v += __shfl_xor_sync(0xffu, v, off);
        if (threadIdx.x == 0)
            out[ZQ_ELEMS] = 2.25f * v / (float)ZQ_ELEMS;
    }
}

// =====================================================================
extern "C" void kernel_launch(void* const* d_in, const int* in_sizes, int n_in,
                              void* d_out, int out_size) {
    const float* z = (const float*)d_in[0];   // (8, 256, 32, 32)
    const float* W = (const float*)d_in[1];   // (8192, 256)
    float* out = (float*)d_out;

    cudaFuncSetAttribute(pass1_kernel,
                         cudaFuncAttributeMaxDynamicSharedMemorySize, P1_SMEM);

    int write_ind = (out_size >= ZQ_ELEMS + 1 + BPOS) ? 1 : 0;

    prep_kernel<<<1568, 256>>>(z, W);
    pass1_kernel<<<dim3(128, NSPLIT), P1THREADS, P1_SMEM>>>();
    pass2_kernel<<<BPOS / 8, 256>>>(z, W);
    zq_loss_kernel<<<ZQ_ELEMS / 1024, 256>>>(z, W, out, write_ind);
    if (out_size > ZQ_ELEMS) {
        finalize_kernel<<<1, 256>>>(out);
    }
}